// round 3
// baseline (speedup 1.0000x reference)
#include <cuda_runtime.h>

namespace {
constexpr int N   = 512;
constexpr int D   = 64;
constexpr int C   = 32;
constexpr int HID = 128;
constexpr int NH  = 8;
constexpr int HD  = 16;
constexpr float SCALE = 0.25f;   // HEAD_DIM^-0.5 = 16^-0.5
constexpr int THREADS = 256;
constexpr int NBT = 96;          // B*T

constexpr int WPAD  = 65;        // weight row pad (kills 16-way bank conflict)
constexpr int XPAD  = 65;        // x chunk row pad
constexpr int KVPAD = 20;        // K/V row pad: 80B (16B-aligned, LDS.128 phase-conflict-free)

constexpr int SW_OFF = 0;
constexpr int SW_SZ  = 3 * HD * WPAD;     // 3120 floats
constexpr int SX_OFF = SW_OFF + SW_SZ;
constexpr int SX_SZ  = 128 * XPAD;        // 8320
constexpr int SQ_OFF = SX_OFF + SX_SZ;    // 11440 (16B aligned)
constexpr int SQ_SZ  = N * HD;            // 8192
constexpr int SK_OFF = SQ_OFF + SQ_SZ;    // 19632 (16B aligned)
constexpr int SK_SZ  = N * KVPAD;         // 10240
constexpr int SV_OFF = SK_OFF + SK_SZ;
constexpr int SV_SZ  = N * KVPAD;
constexpr int SMEM_FLOATS = SV_OFF + SV_SZ;   // 40112 floats = 160448 B
}

__global__ __launch_bounds__(THREADS, 1)
void spatial_attn_kernel(const float* __restrict__ x,
                         const float* __restrict__ cls,
                         const float* __restrict__ Wq,
                         const float* __restrict__ Wk,
                         const float* __restrict__ Wv,
                         float* __restrict__ out) {
    extern __shared__ float smem[];
    float* sW = smem + SW_OFF;
    float* sX = smem + SX_OFF;
    float* sQ = smem + SQ_OFF;   // [512][16]; later reused for sx
    float* sK = smem + SK_OFF;   // [512][20]
    float* sV = smem + SV_OFF;   // [512][20]

    const int blk = blockIdx.x;
    const int h   = blk & (NH - 1);
    const int bt  = blk >> 3;
    const float* xg   = x   + (size_t)bt * N * D;
    const float* clsg = cls + (size_t)bt * C * N;

    const int tid  = threadIdx.x;
    const int lane = tid & 31;
    const int wid  = tid >> 5;

    // ---- load this head's 16 weight rows of each of Wq/Wk/Wv (padded) ----
    for (int idx = tid; idx < HD * D; idx += THREADS) {
        const int e = idx >> 6;
        const int d = idx & 63;
        sW[0 * HD * WPAD + e * WPAD + d] = Wq[(h * HD + e) * D + d];
        sW[1 * HD * WPAD + e * WPAD + d] = Wk[(h * HD + e) * D + d];
        sW[2 * HD * WPAD + e * WPAD + d] = Wv[(h * HD + e) * D + d];
    }

    // ---- projections: 4 chunks of 128 rows staged in SMEM ----
    const int e    = lane & 15;
    const int half = lane >> 4;
    for (int ch = 0; ch < 4; ch++) {
        __syncthreads();                       // protect sX reuse (and weights on ch=0)
        for (int idx = tid; idx < 128 * D; idx += THREADS) {
            const int r = idx >> 6;
            const int d = idx & 63;
            sX[r * XPAD + d] = xg[(ch * 128 + r) * D + d];
        }
        __syncthreads();
        // warp wid owns rows [wid*16, wid*16+16) of this chunk
        for (int rr = half; rr < 16; rr += 2) {
            const int r = wid * 16 + rr;
            const float* xr = sX + r * XPAD;
            const float* wq = sW + 0 * HD * WPAD + e * WPAD;
            const float* wk = sW + 1 * HD * WPAD + e * WPAD;
            const float* wv = sW + 2 * HD * WPAD + e * WPAD;
            float aq = 0.f, ak = 0.f, av = 0.f;
            #pragma unroll
            for (int d = 0; d < D; d++) {
                const float xv = xr[d];
                aq = fmaf(xv, wq[d], aq);
                ak = fmaf(xv, wk[d], ak);
                av = fmaf(xv, wv[d], av);
            }
            const int gr = ch * 128 + r;
            sQ[gr * HD    + e] = aq;
            sK[gr * KVPAD + e] = ak;
            sV[gr * KVPAD + e] = av;
        }
    }
    __syncthreads();

    // ---- attention: warp wid handles query rows [wid*64, wid*64+64), 4 at a time ----
    for (int g = 0; g < 16; g++) {
        const int n0 = wid * 64 + g * 4;

        float q[4][16];
        #pragma unroll
        for (int r = 0; r < 4; r++) {
            const float4* qr = reinterpret_cast<const float4*>(sQ + (n0 + r) * HD);
            #pragma unroll
            for (int j = 0; j < 4; j++) {
                const float4 v4 = qr[j];
                q[r][4*j+0] = v4.x * SCALE;
                q[r][4*j+1] = v4.y * SCALE;
                q[r][4*j+2] = v4.z * SCALE;
                q[r][4*j+3] = v4.w * SCALE;
            }
        }

        // QK^T: lane covers keys m = i*32 + lane
        float s[4][16];
        #pragma unroll
        for (int i = 0; i < 16; i++) {
            const int m = i * 32 + lane;
            const float4* kr = reinterpret_cast<const float4*>(sK + m * KVPAD);
            float kv[16];
            #pragma unroll
            for (int j = 0; j < 4; j++) {
                const float4 v4 = kr[j];
                kv[4*j+0]=v4.x; kv[4*j+1]=v4.y; kv[4*j+2]=v4.z; kv[4*j+3]=v4.w;
            }
            #pragma unroll
            for (int r = 0; r < 4; r++) {
                float acc = 0.f;
                #pragma unroll
                for (int d2 = 0; d2 < 16; d2++)
                    acc = fmaf(q[r][d2], kv[d2], acc);
                s[r][i] = acc;
            }
        }

        // softmax stats (warp-wide butterfly); s -> p in place
        float sm[4];
        #pragma unroll
        for (int r = 0; r < 4; r++) {
            float m1 = s[r][0];
            #pragma unroll
            for (int i = 1; i < 16; i++) m1 = fmaxf(m1, s[r][i]);
            #pragma unroll
            for (int off = 16; off > 0; off >>= 1)
                m1 = fmaxf(m1, __shfl_xor_sync(0xffffffffu, m1, off));
            float ss = 0.f;
            #pragma unroll
            for (int i = 0; i < 16; i++) {
                const float p = __expf(s[r][i] - m1);
                s[r][i] = p;
                ss += p;
            }
            #pragma unroll
            for (int off = 16; off > 0; off >>= 1)
                ss += __shfl_xor_sync(0xffffffffu, ss, off);
            sm[r] = ss;
        }

        // P @ V
        float acc[4][16];
        #pragma unroll
        for (int r = 0; r < 4; r++)
            #pragma unroll
            for (int d2 = 0; d2 < 16; d2++) acc[r][d2] = 0.f;
        #pragma unroll
        for (int i = 0; i < 16; i++) {
            const int m = i * 32 + lane;
            const float4* vr = reinterpret_cast<const float4*>(sV + m * KVPAD);
            float vv[16];
            #pragma unroll
            for (int j = 0; j < 4; j++) {
                const float4 v4 = vr[j];
                vv[4*j+0]=v4.x; vv[4*j+1]=v4.y; vv[4*j+2]=v4.z; vv[4*j+3]=v4.w;
            }
            #pragma unroll
            for (int r = 0; r < 4; r++) {
                const float p = s[r][i];
                #pragma unroll
                for (int d2 = 0; d2 < 16; d2++)
                    acc[r][d2] = fmaf(p, vv[d2], acc[r][d2]);
            }
        }

        // cross-lane reduce acc, normalize, write sx back into sQ rows we consumed
        #pragma unroll
        for (int r = 0; r < 4; r++) {
            const float inv = 1.0f / sm[r];
            float outv = 0.f;
            #pragma unroll
            for (int d2 = 0; d2 < 16; d2++) {
                float a = acc[r][d2];
                #pragma unroll
                for (int off = 16; off > 0; off >>= 1)
                    a += __shfl_xor_sync(0xffffffffu, a, off);
                if (lane == d2) outv = a * inv;
            }
            if (lane < 16) sQ[(n0 + r) * HD + lane] = outv;
        }
    }
    __syncthreads();

    // ---- cls pooling: pooled[c][d] = sum_n cls[c][n] * sx[n][d] ----
    const int c  = tid >> 3;        // 0..31
    const int d0 = (tid & 7) * 2;   // 0,2,...,14
    float a0 = 0.f, a1 = 0.f;
    const float* clc = clsg + c * N;
    #pragma unroll 8
    for (int n = 0; n < N; n++) {
        const float cl = __ldg(clc + n);
        const float2 sx2 = *reinterpret_cast<const float2*>(sQ + n * HD + d0);
        a0 = fmaf(cl, sx2.x, a0);
        a1 = fmaf(cl, sx2.y, a1);
    }
    float* og = out + ((size_t)bt * C + c) * HID + h * HD + d0;
    og[0] = a0;
    og[1] = a1;
}

extern "C" void kernel_launch(void* const* d_in, const int* in_sizes, int n_in,
                              void* d_out, int out_size) {
    const float* x   = (const float*)d_in[0];
    const float* cls = (const float*)d_in[1];
    const float* Wq  = (const float*)d_in[2];
    const float* Wk  = (const float*)d_in[3];
    const float* Wv  = (const float*)d_in[4];
    float* out = (float*)d_out;

    const size_t smem_bytes = (size_t)SMEM_FLOATS * sizeof(float);  // ~157 KB
    cudaFuncSetAttribute(spatial_attn_kernel,
                         cudaFuncAttributeMaxDynamicSharedMemorySize,
                         (int)smem_bytes);
    spatial_attn_kernel<<<NBT * NH, THREADS, smem_bytes>>>(x, cls, Wq, Wk, Wv, out);
}

// round 4
// speedup vs baseline: 1.0762x; 1.0762x over previous
#include <cuda_runtime.h>

namespace {
constexpr int N   = 512;
constexpr int D   = 64;
constexpr int C   = 32;
constexpr int HID = 128;
constexpr int NH  = 8;
constexpr int HD  = 16;
constexpr float SCALE = 0.25f;   // HEAD_DIM^-0.5
constexpr int THREADS = 512;
constexpr int NBT = 96;          // B*T

constexpr int WSTRIDE = 68;      // weight row stride: float4-aligned, phase-conflict-free
constexpr int KVPAD   = 20;      // K/V row stride: 80B, LDS.128 phase-conflict-free

constexpr int SW_OFF = 0;
constexpr int SW_SZ  = 3 * HD * WSTRIDE;    // 3264
constexpr int SX_OFF = SW_OFF + SW_SZ;      // 3264
constexpr int SX_SZ  = 256 * D;             // 16384 (256-row x chunk)
constexpr int SQ_OFF = SX_OFF + SX_SZ;      // 19648
constexpr int SQ_SZ  = N * HD;              // 8192
constexpr int SK_OFF = SQ_OFF + SQ_SZ;      // 27840
constexpr int SK_SZ  = N * KVPAD;           // 10240
constexpr int SV_OFF = SK_OFF + SK_SZ;      // 38080
constexpr int SV_SZ  = N * KVPAD;           // 10240
constexpr int SMEM_FLOATS = SV_OFF + SV_SZ; // 48320 floats = 193280 B

constexpr int CLS_OFF    = SK_OFF;          // overlay cls_map onto dead K/V
constexpr int CLS_STRIDE = 516;             // 32*516 = 16512 <= 20480 available
}

__global__ __launch_bounds__(THREADS, 1)
void spatial_attn_kernel(const float* __restrict__ x,
                         const float* __restrict__ cls,
                         const float* __restrict__ Wq,
                         const float* __restrict__ Wk,
                         const float* __restrict__ Wv,
                         float* __restrict__ out) {
    extern __shared__ float smem[];

    const int blk = blockIdx.x;
    const int h   = blk & (NH - 1);
    const int bt  = blk >> 3;
    const float* xg   = x   + (size_t)bt * N * D;
    const float* clsg = cls + (size_t)bt * C * N;

    const int tid  = threadIdx.x;
    const int lane = tid & 31;
    const int wid  = tid >> 5;

    // ---- stage this head's weights: sW[kind][e][d], stride WSTRIDE ----
    for (int idx = tid; idx < 3 * HD * D; idx += THREADS) {
        const int kind = idx >> 10;
        const int rem  = idx & 1023;
        const int e    = rem >> 6;
        const int d    = rem & 63;
        const float* Wsrc = (kind == 0) ? Wq : (kind == 1) ? Wk : Wv;
        smem[SW_OFF + kind * HD * WSTRIDE + e * WSTRIDE + d] = Wsrc[(h * HD + e) * D + d];
    }

    // ---- projections: 2 chunks of 256 rows ----
    const int e    = lane & 15;
    const int half = lane >> 4;
    const float* sWq = smem + SW_OFF + 0 * HD * WSTRIDE + e * WSTRIDE;
    const float* sWk = smem + SW_OFF + 1 * HD * WSTRIDE + e * WSTRIDE;
    const float* sWv = smem + SW_OFF + 2 * HD * WSTRIDE + e * WSTRIDE;

    for (int ch = 0; ch < 2; ch++) {
        __syncthreads();   // protect sX reuse (and weights on ch=0)
        {
            const float4* src = reinterpret_cast<const float4*>(xg + (size_t)ch * 256 * D);
            float4* dst = reinterpret_cast<float4*>(smem + SX_OFF);
            #pragma unroll
            for (int i = tid; i < 256 * D / 4; i += THREADS) dst[i] = src[i];
        }
        __syncthreads();

        // warp owns 16 rows: half0 -> even offsets, half1 -> odd (conflict-free stores)
        const int rbase = wid * 16 + half;
        float aq[8], ak[8], av[8];
        #pragma unroll
        for (int r = 0; r < 8; r++) { aq[r] = 0.f; ak[r] = 0.f; av[r] = 0.f; }

        #pragma unroll 4
        for (int d4 = 0; d4 < 16; d4++) {
            const float4 wq4 = *reinterpret_cast<const float4*>(sWq + d4 * 4);
            const float4 wk4 = *reinterpret_cast<const float4*>(sWk + d4 * 4);
            const float4 wv4 = *reinterpret_cast<const float4*>(sWv + d4 * 4);
            #pragma unroll
            for (int r = 0; r < 8; r++) {
                const float4 x4 = *reinterpret_cast<const float4*>(
                    smem + SX_OFF + (rbase + 2 * r) * D + d4 * 4);
                aq[r] = fmaf(x4.x, wq4.x, aq[r]);
                aq[r] = fmaf(x4.y, wq4.y, aq[r]);
                aq[r] = fmaf(x4.z, wq4.z, aq[r]);
                aq[r] = fmaf(x4.w, wq4.w, aq[r]);
                ak[r] = fmaf(x4.x, wk4.x, ak[r]);
                ak[r] = fmaf(x4.y, wk4.y, ak[r]);
                ak[r] = fmaf(x4.z, wk4.z, ak[r]);
                ak[r] = fmaf(x4.w, wk4.w, ak[r]);
                av[r] = fmaf(x4.x, wv4.x, av[r]);
                av[r] = fmaf(x4.y, wv4.y, av[r]);
                av[r] = fmaf(x4.z, wv4.z, av[r]);
                av[r] = fmaf(x4.w, wv4.w, av[r]);
            }
        }
        #pragma unroll
        for (int r = 0; r < 8; r++) {
            const int gr = ch * 256 + rbase + 2 * r;
            smem[SQ_OFF + gr * HD    + e] = aq[r] * SCALE;   // fold SCALE into Q
            smem[SK_OFF + gr * KVPAD + e] = ak[r];
            smem[SV_OFF + gr * KVPAD + e] = av[r];
        }
    }
    __syncthreads();

    // ---- attention: warp handles rows [wid*32, wid*32+32), 4 at a time ----
    for (int g = 0; g < 8; g++) {
        const int n0 = wid * 32 + g * 4;

        float q[4][16];
        #pragma unroll
        for (int r = 0; r < 4; r++) {
            const float4* qr = reinterpret_cast<const float4*>(smem + SQ_OFF + (n0 + r) * HD);
            #pragma unroll
            for (int j = 0; j < 4; j++) {
                const float4 v4 = qr[j];
                q[r][4*j+0] = v4.x; q[r][4*j+1] = v4.y;
                q[r][4*j+2] = v4.z; q[r][4*j+3] = v4.w;
            }
        }

        // QK^T: lane covers keys m = i*32 + lane
        float s[4][16];
        #pragma unroll
        for (int i = 0; i < 16; i++) {
            const int m = i * 32 + lane;
            const float4* kr = reinterpret_cast<const float4*>(smem + SK_OFF + m * KVPAD);
            float kv[16];
            #pragma unroll
            for (int j = 0; j < 4; j++) {
                const float4 v4 = kr[j];
                kv[4*j+0]=v4.x; kv[4*j+1]=v4.y; kv[4*j+2]=v4.z; kv[4*j+3]=v4.w;
            }
            #pragma unroll
            for (int r = 0; r < 4; r++) {
                float acc = 0.f;
                #pragma unroll
                for (int d2 = 0; d2 < 16; d2++)
                    acc = fmaf(q[r][d2], kv[d2], acc);
                s[r][i] = acc;
            }
        }

        // softmax (no max subtraction: |s| <~ 13, fp32-safe); s -> p in place
        float inv[4];
        #pragma unroll
        for (int r = 0; r < 4; r++) {
            float ss = 0.f;
            #pragma unroll
            for (int i = 0; i < 16; i++) {
                const float p = __expf(s[r][i]);
                s[r][i] = p;
                ss += p;
            }
            #pragma unroll
            for (int off = 16; off > 0; off >>= 1)
                ss += __shfl_xor_sync(0xffffffffu, ss, off);
            inv[r] = __frcp_rn(ss);
        }

        // P @ V
        float acc[4][16];
        #pragma unroll
        for (int r = 0; r < 4; r++)
            #pragma unroll
            for (int d2 = 0; d2 < 16; d2++) acc[r][d2] = 0.f;
        #pragma unroll
        for (int i = 0; i < 16; i++) {
            const int m = i * 32 + lane;
            const float4* vr = reinterpret_cast<const float4*>(smem + SV_OFF + m * KVPAD);
            float vv[16];
            #pragma unroll
            for (int j = 0; j < 4; j++) {
                const float4 v4 = vr[j];
                vv[4*j+0]=v4.x; vv[4*j+1]=v4.y; vv[4*j+2]=v4.z; vv[4*j+3]=v4.w;
            }
            #pragma unroll
            for (int r = 0; r < 4; r++) {
                const float p = s[r][i];
                #pragma unroll
                for (int d2 = 0; d2 < 16; d2++)
                    acc[r][d2] = fmaf(p, vv[d2], acc[r][d2]);
            }
        }

        // log-fold transpose-reduce: 31 shfl per row; lane l<16 ends with dim l
        #pragma unroll
        for (int r = 0; r < 4; r++) {
            float* a = acc[r];
            #pragma unroll
            for (int d2 = 0; d2 < 16; d2++)
                a[d2] += __shfl_xor_sync(0xffffffffu, a[d2], 16);
            #pragma unroll
            for (int b = 8; b >= 1; b >>= 1) {
                #pragma unroll
                for (int j = 0; j < b; j++) {
                    const int keep = (lane & b) ? (b + j) : j;
                    const int send = (lane & b) ? j : (b + j);
                    const float recv = __shfl_xor_sync(0xffffffffu, a[send], b);
                    a[j] = a[keep] + recv;
                }
            }
            if (lane < 16)
                smem[SQ_OFF + (n0 + r) * HD + lane] = a[0] * inv[r];
        }
    }
    __syncthreads();

    // ---- stage cls_map into dead K/V smem ----
    {
        const float4* src = reinterpret_cast<const float4*>(clsg);
        #pragma unroll
        for (int i = tid; i < C * N / 4; i += THREADS) {
            const int c  = i >> 7;          // 128 float4 per cls row
            const int n4 = i & 127;
            *reinterpret_cast<float4*>(smem + CLS_OFF + c * CLS_STRIDE + n4 * 4) = src[i];
        }
    }
    __syncthreads();

    // ---- cls pooling: thread (c = tid>>4, d = tid&15) ----
    {
        const int c = tid >> 4;
        const int d = tid & 15;
        const float* pc  = smem + CLS_OFF + c * CLS_STRIDE;
        const float* psx = smem + SQ_OFF + d;
        float a0 = 0.f, a1 = 0.f, a2 = 0.f, a3 = 0.f;
        #pragma unroll 4
        for (int n = 0; n < N; n += 4) {
            const float4 cl = *reinterpret_cast<const float4*>(pc + n);
            a0 = fmaf(cl.x, psx[(n + 0) * HD], a0);
            a1 = fmaf(cl.y, psx[(n + 1) * HD], a1);
            a2 = fmaf(cl.z, psx[(n + 2) * HD], a2);
            a3 = fmaf(cl.w, psx[(n + 3) * HD], a3);
        }
        out[((size_t)bt * C + c) * HID + h * HD + d] = (a0 + a1) + (a2 + a3);
    }
}

extern "C" void kernel_launch(void* const* d_in, const int* in_sizes, int n_in,
                              void* d_out, int out_size) {
    const float* x   = (const float*)d_in[0];
    const float* cls = (const float*)d_in[1];
    const float* Wq  = (const float*)d_in[2];
    const float* Wk  = (const float*)d_in[3];
    const float* Wv  = (const float*)d_in[4];
    float* out = (float*)d_out;

    const size_t smem_bytes = (size_t)SMEM_FLOATS * sizeof(float);  // ~189 KB
    cudaFuncSetAttribute(spatial_attn_kernel,
                         cudaFuncAttributeMaxDynamicSharedMemorySize,
                         (int)smem_bytes);
    spatial_attn_kernel<<<NBT * NH, THREADS, smem_bytes>>>(x, cls, Wq, Wk, Wv, out);
}

// round 5
// speedup vs baseline: 1.5066x; 1.3999x over previous
#include <cuda_runtime.h>

namespace {
constexpr int N   = 512;
constexpr int D   = 64;
constexpr int C   = 32;
constexpr int HID = 128;
constexpr int NH  = 8;
constexpr int HD  = 16;
constexpr float SCALE = 0.25f;   // HEAD_DIM^-0.5
constexpr int THREADS = 512;
constexpr int NBT = 96;          // B*T

constexpr int WSTRIDE = 68;      // weight row stride (floats): 16B-aligned, conflict-free
constexpr int KVPAD   = 20;      // K/V row stride: 80B, LDS.128 phase-conflict-free

constexpr int SW_OFF = 0;
constexpr int SW_SZ  = 3 * HD * WSTRIDE;    // 3264
constexpr int SX_OFF = SW_OFF + SW_SZ;      // 3264
constexpr int SX_SZ  = 256 * D;             // 16384
constexpr int SQ_OFF = SX_OFF + SX_SZ;      // 19648
constexpr int SQ_SZ  = N * HD;              // 8192
constexpr int SK_OFF = SQ_OFF + SQ_SZ;      // 27840
constexpr int SK_SZ  = N * KVPAD;           // 10240
constexpr int SV_OFF = SK_OFF + SK_SZ;      // 38080
constexpr int SV_SZ  = N * KVPAD;           // 10240
constexpr int SMEM_FLOATS = SV_OFF + SV_SZ; // 48320 floats = 193280 B

constexpr int CLS_OFF    = SK_OFF;          // overlay cls_map onto dead K/V
constexpr int CLS_STRIDE = 516;
}

// ---- packed fp32x2 helpers (Blackwell FFMA2 path; ptxas never emits from C++) ----
__device__ __forceinline__ unsigned long long f2_pack(float lo, float hi) {
    unsigned long long r;
    asm("mov.b64 %0, {%1, %2};" : "=l"(r) : "f"(lo), "f"(hi));
    return r;
}
__device__ __forceinline__ void f2_unpack(unsigned long long v, float& lo, float& hi) {
    asm("mov.b64 {%0, %1}, %2;" : "=f"(lo), "=f"(hi) : "l"(v));
}
__device__ __forceinline__ unsigned long long f2_mul(unsigned long long a, unsigned long long b) {
    unsigned long long d;
    asm("mul.rn.f32x2 %0, %1, %2;" : "=l"(d) : "l"(a), "l"(b));
    return d;
}
__device__ __forceinline__ unsigned long long f2_fma(unsigned long long a, unsigned long long b,
                                                     unsigned long long c) {
    unsigned long long d;
    asm("fma.rn.f32x2 %0, %1, %2, %3;" : "=l"(d) : "l"(a), "l"(b), "l"(c));
    return d;
}

__global__ __launch_bounds__(THREADS, 1)
void spatial_attn_kernel(const float* __restrict__ x,
                         const float* __restrict__ cls,
                         const float* __restrict__ Wq,
                         const float* __restrict__ Wk,
                         const float* __restrict__ Wv,
                         float* __restrict__ out) {
    extern __shared__ float smem[];

    const int blk = blockIdx.x;
    const int h   = blk & (NH - 1);
    const int bt  = blk >> 3;
    const float* xg   = x   + (size_t)bt * N * D;
    const float* clsg = cls + (size_t)bt * C * N;

    const int tid  = threadIdx.x;
    const int lane = tid & 31;
    const int wid  = tid >> 5;

    // ---- stage this head's weights ----
    for (int idx = tid; idx < 3 * HD * D; idx += THREADS) {
        const int kind = idx >> 10;
        const int rem  = idx & 1023;
        const int e    = rem >> 6;
        const int d    = rem & 63;
        const float* Wsrc = (kind == 0) ? Wq : (kind == 1) ? Wk : Wv;
        smem[SW_OFF + kind * HD * WSTRIDE + e * WSTRIDE + d] = Wsrc[(h * HD + e) * D + d];
    }

    // ---- projections: 2 chunks of 256 rows, packed f32x2 inner ----
    const int e    = lane & 15;
    const int half = lane >> 4;
    const float* sWq = smem + SW_OFF + 0 * HD * WSTRIDE + e * WSTRIDE;
    const float* sWk = smem + SW_OFF + 1 * HD * WSTRIDE + e * WSTRIDE;
    const float* sWv = smem + SW_OFF + 2 * HD * WSTRIDE + e * WSTRIDE;

    for (int ch = 0; ch < 2; ch++) {
        __syncthreads();   // protect sX reuse (and weights on ch=0)
        {
            const float4* src = reinterpret_cast<const float4*>(xg + (size_t)ch * 256 * D);
            float4* dst = reinterpret_cast<float4*>(smem + SX_OFF);
            #pragma unroll
            for (int i = tid; i < 256 * D / 4; i += THREADS) dst[i] = src[i];
        }
        __syncthreads();

        const int rbase = wid * 16 + half;
        unsigned long long aq2[8], ak2[8], av2[8];
        #pragma unroll
        for (int r = 0; r < 8; r++) { aq2[r] = 0ULL; ak2[r] = 0ULL; av2[r] = 0ULL; }

        #pragma unroll 4
        for (int d4 = 0; d4 < 16; d4++) {
            const ulonglong2 wq2 = *reinterpret_cast<const ulonglong2*>(sWq + d4 * 4);
            const ulonglong2 wk2 = *reinterpret_cast<const ulonglong2*>(sWk + d4 * 4);
            const ulonglong2 wv2 = *reinterpret_cast<const ulonglong2*>(sWv + d4 * 4);
            #pragma unroll
            for (int r = 0; r < 8; r++) {
                const ulonglong2 x2 = *reinterpret_cast<const ulonglong2*>(
                    smem + SX_OFF + (rbase + 2 * r) * D + d4 * 4);
                aq2[r] = f2_fma(x2.x, wq2.x, aq2[r]);
                aq2[r] = f2_fma(x2.y, wq2.y, aq2[r]);
                ak2[r] = f2_fma(x2.x, wk2.x, ak2[r]);
                ak2[r] = f2_fma(x2.y, wk2.y, ak2[r]);
                av2[r] = f2_fma(x2.x, wv2.x, av2[r]);
                av2[r] = f2_fma(x2.y, wv2.y, av2[r]);
            }
        }
        #pragma unroll
        for (int r = 0; r < 8; r++) {
            const int gr = ch * 256 + rbase + 2 * r;
            float lo, hi;
            f2_unpack(aq2[r], lo, hi);
            smem[SQ_OFF + gr * HD    + e] = (lo + hi) * SCALE;   // fold SCALE into Q
            f2_unpack(ak2[r], lo, hi);
            smem[SK_OFF + gr * KVPAD + e] = lo + hi;
            f2_unpack(av2[r], lo, hi);
            smem[SV_OFF + gr * KVPAD + e] = lo + hi;
        }
    }
    __syncthreads();

    // ---- attention: warp handles rows [wid*32, wid*32+32), 4 at a time ----
    for (int g = 0; g < 8; g++) {
        const int n0 = wid * 32 + g * 4;

        // QK^T in two d-half passes (keeps live regs under the 128 cap)
        float s[4][16];
        #pragma unroll
        for (int pass = 0; pass < 2; pass++) {
            ulonglong2 qa[4];   // 4 packed pairs per row (8 dims)
            #pragma unroll
            for (int r = 0; r < 4; r++)
                qa[r] = *reinterpret_cast<const ulonglong2*>(
                    smem + SQ_OFF + (n0 + r) * HD + pass * 8);
            ulonglong2 qb[4];
            #pragma unroll
            for (int r = 0; r < 4; r++)
                qb[r] = *reinterpret_cast<const ulonglong2*>(
                    smem + SQ_OFF + (n0 + r) * HD + pass * 8 + 4);

            #pragma unroll
            for (int i = 0; i < 16; i++) {
                const float* kbase = smem + SK_OFF + (i * 32 + lane) * KVPAD + pass * 8;
                const ulonglong2 k01 = *reinterpret_cast<const ulonglong2*>(kbase);
                const ulonglong2 k23 = *reinterpret_cast<const ulonglong2*>(kbase + 4);
                #pragma unroll
                for (int r = 0; r < 4; r++) {
                    unsigned long long t = f2_mul(qa[r].x, k01.x);
                    t = f2_fma(qa[r].y, k01.y, t);
                    t = f2_fma(qb[r].x, k23.x, t);
                    t = f2_fma(qb[r].y, k23.y, t);
                    float lo, hi;
                    f2_unpack(t, lo, hi);
                    if (pass == 0) s[r][i] = lo + hi;
                    else           s[r][i] = s[r][i] + lo + hi;
                }
            }
        }

        // softmax (no max subtraction: |s| <~ 13, fp32-safe); s -> p in place
        float inv[4];
        #pragma unroll
        for (int r = 0; r < 4; r++) {
            float ss = 0.f;
            #pragma unroll
            for (int i = 0; i < 16; i++) {
                const float p = __expf(s[r][i]);
                s[r][i] = p;
                ss += p;
            }
            #pragma unroll
            for (int off = 16; off > 0; off >>= 1)
                ss += __shfl_xor_sync(0xffffffffu, ss, off);
            inv[r] = __frcp_rn(ss);
        }

        // P @ V in two d-half passes, packed accumulators
        #pragma unroll
        for (int pass = 0; pass < 2; pass++) {
            unsigned long long acc2[4][4];
            #pragma unroll
            for (int r = 0; r < 4; r++)
                #pragma unroll
                for (int j = 0; j < 4; j++) acc2[r][j] = 0ULL;

            #pragma unroll
            for (int i = 0; i < 16; i++) {
                const float* vbase = smem + SV_OFF + (i * 32 + lane) * KVPAD + pass * 8;
                const ulonglong2 v01 = *reinterpret_cast<const ulonglong2*>(vbase);
                const ulonglong2 v23 = *reinterpret_cast<const ulonglong2*>(vbase + 4);
                #pragma unroll
                for (int r = 0; r < 4; r++) {
                    const unsigned long long p2 = f2_pack(s[r][i], s[r][i]);
                    acc2[r][0] = f2_fma(p2, v01.x, acc2[r][0]);
                    acc2[r][1] = f2_fma(p2, v01.y, acc2[r][1]);
                    acc2[r][2] = f2_fma(p2, v23.x, acc2[r][2]);
                    acc2[r][3] = f2_fma(p2, v23.y, acc2[r][3]);
                }
            }

            // reduce 8 dims across 32 lanes; lane l<8 ends with dim l
            #pragma unroll
            for (int r = 0; r < 4; r++) {
                float a[8];
                #pragma unroll
                for (int j = 0; j < 4; j++)
                    f2_unpack(acc2[r][j], a[2 * j], a[2 * j + 1]);
                #pragma unroll
                for (int d2 = 0; d2 < 8; d2++)
                    a[d2] += __shfl_xor_sync(0xffffffffu, a[d2], 16);
                #pragma unroll
                for (int d2 = 0; d2 < 8; d2++)
                    a[d2] += __shfl_xor_sync(0xffffffffu, a[d2], 8);
                #pragma unroll
                for (int b = 4; b >= 1; b >>= 1) {
                    #pragma unroll
                    for (int j = 0; j < b; j++) {
                        const int keep = (lane & b) ? (b + j) : j;
                        const int send = (lane & b) ? j : (b + j);
                        const float recv = __shfl_xor_sync(0xffffffffu, a[send], b);
                        a[j] = a[keep] + recv;
                    }
                }
                if (lane < 8)
                    smem[SQ_OFF + (n0 + r) * HD + pass * 8 + lane] = a[0] * inv[r];
            }
        }
    }
    __syncthreads();

    // ---- stage cls_map into dead K/V smem ----
    {
        const float4* src = reinterpret_cast<const float4*>(clsg);
        #pragma unroll
        for (int i = tid; i < C * N / 4; i += THREADS) {
            const int c  = i >> 7;
            const int n4 = i & 127;
            *reinterpret_cast<float4*>(smem + CLS_OFF + c * CLS_STRIDE + n4 * 4) = src[i];
        }
    }
    __syncthreads();

    // ---- cls pooling: thread (c = tid>>4, d = tid&15) ----
    {
        const int c = tid >> 4;
        const int d = tid & 15;
        const float* pc  = smem + CLS_OFF + c * CLS_STRIDE;
        const float* psx = smem + SQ_OFF + d;
        float a0 = 0.f, a1 = 0.f, a2 = 0.f, a3 = 0.f;
        #pragma unroll 4
        for (int n = 0; n < N; n += 4) {
            const float4 cl = *reinterpret_cast<const float4*>(pc + n);
            a0 = fmaf(cl.x, psx[(n + 0) * HD], a0);
            a1 = fmaf(cl.y, psx[(n + 1) * HD], a1);
            a2 = fmaf(cl.z, psx[(n + 2) * HD], a2);
            a3 = fmaf(cl.w, psx[(n + 3) * HD], a3);
        }
        out[((size_t)bt * C + c) * HID + h * HD + d] = (a0 + a1) + (a2 + a3);
    }
}

extern "C" void kernel_launch(void* const* d_in, const int* in_sizes, int n_in,
                              void* d_out, int out_size) {
    const float* x   = (const float*)d_in[0];
    const float* cls = (const float*)d_in[1];
    const float* Wq  = (const float*)d_in[2];
    const float* Wk  = (const float*)d_in[3];
    const float* Wv  = (const float*)d_in[4];
    float* out = (float*)d_out;

    const size_t smem_bytes = (size_t)SMEM_FLOATS * sizeof(float);  // ~189 KB
    cudaFuncSetAttribute(spatial_attn_kernel,
                         cudaFuncAttributeMaxDynamicSharedMemorySize,
                         (int)smem_bytes);
    spatial_attn_kernel<<<NBT * NH, THREADS, smem_bytes>>>(x, cls, Wq, Wk, Wv, out);
}